// round 2
// baseline (speedup 1.0000x reference)
#include <cuda_runtime.h>
#include <math.h>

#define B_    8
#define N_    4096
#define C_    768
#define H_    12
#define HD_   64
#define NWIN_ 16
#define WT_   256
#define KT_   64          /* kv tile for attention smem */
#define C3_   2304
#define M_    (B_ * N_)   /* 32768 */
#define SCALE_ 0.125f

// Scratch (device globals; no allocation allowed in kernel_launch)
__device__ float g_qkv[(size_t)M_ * C3_];  // qkv in window-permuted row order
__device__ float g_ao [(size_t)M_ * C_];   // attention output, permuted order

// permuted position p -> original token index
// p = a*1024 + c*256 + b*16 + d  maps to  orig = a*1024 + b*64 + c*16 + d
__device__ __forceinline__ int perm_orig(int p) {
    int a = p >> 10, c = (p >> 8) & 3, bq = (p >> 4) & 15, d = p & 15;
    return (a << 10) | (bq << 6) | (c << 4) | d;
}

// ---------------------------------------------------------------------------
// Tiled fp32 GEMM:  C[M x NOUT] = A[M x 768] @ W[NOUT x 768]^T (+ bias)
// MODE 0: A = x with window-permuted row reads, C = g_qkv
// MODE 1: A = g_ao, C = out with inverse-permuted row stores, + bias
// BM=BN=128, BK=16, 256 threads, 8x8 register tile per thread.
// ---------------------------------------------------------------------------
template<int NOUT, int MODE>
__global__ __launch_bounds__(256) void sgemm_k(const float* __restrict__ Ain,
                                               const float* __restrict__ Wt,
                                               const float* __restrict__ bias,
                                               float* __restrict__ Cext)
{
    constexpr int BM = 128, BN = 128, BK = 16;
    __shared__ float As[BK][BM + 4];
    __shared__ float Bs[BK][BN + 4];

    const int tid = threadIdx.x;
    const int bm  = blockIdx.y * BM;
    const int bn  = blockIdx.x * BN;

    const float* A    = (MODE == 0) ? Ain : g_ao;
    float*       Cout = (MODE == 0) ? g_qkv : Cext;

    float acc[8][8];
    #pragma unroll
    for (int i = 0; i < 8; i++)
        #pragma unroll
        for (int j = 0; j < 8; j++) acc[i][j] = 0.f;

    const int lr = tid >> 2;        // 0..63, two rows per thread
    const int lk = (tid & 3) << 2;  // 0,4,8,12

    // Precompute global A rows (permute on read for MODE 0)
    int arow[2];
    #pragma unroll
    for (int i = 0; i < 2; i++) {
        int gm = bm + lr + i * 64;
        arow[i] = (MODE == 0) ? (gm & ~4095) + perm_orig(gm & 4095) : gm;
    }

    const int tr = (tid >> 4) << 3;  // thread tile row base
    const int tc = (tid & 15) << 3;  // thread tile col base

    for (int k0 = 0; k0 < C_; k0 += BK) {
        #pragma unroll
        for (int i = 0; i < 2; i++) {
            int r = lr + i * 64;
            float4 v = *reinterpret_cast<const float4*>(A + (size_t)arow[i] * C_ + k0 + lk);
            As[lk + 0][r] = v.x; As[lk + 1][r] = v.y;
            As[lk + 2][r] = v.z; As[lk + 3][r] = v.w;
        }
        #pragma unroll
        for (int i = 0; i < 2; i++) {
            int n = lr + i * 64;
            float4 v = *reinterpret_cast<const float4*>(Wt + (size_t)(bn + n) * C_ + k0 + lk);
            Bs[lk + 0][n] = v.x; Bs[lk + 1][n] = v.y;
            Bs[lk + 2][n] = v.z; Bs[lk + 3][n] = v.w;
        }
        __syncthreads();

        #pragma unroll
        for (int k = 0; k < BK; k++) {
            float a[8], bv[8];
            *reinterpret_cast<float4*>(&a[0])  = *reinterpret_cast<const float4*>(&As[k][tr]);
            *reinterpret_cast<float4*>(&a[4])  = *reinterpret_cast<const float4*>(&As[k][tr + 4]);
            *reinterpret_cast<float4*>(&bv[0]) = *reinterpret_cast<const float4*>(&Bs[k][tc]);
            *reinterpret_cast<float4*>(&bv[4]) = *reinterpret_cast<const float4*>(&Bs[k][tc + 4]);
            #pragma unroll
            for (int i = 0; i < 8; i++)
                #pragma unroll
                for (int j = 0; j < 8; j++)
                    acc[i][j] = fmaf(a[i], bv[j], acc[i][j]);
        }
        __syncthreads();
    }

    #pragma unroll
    for (int i = 0; i < 8; i++) {
        int gm   = bm + tr + i;
        int crow = (MODE == 1) ? (gm & ~4095) + perm_orig(gm & 4095) : gm;
        float* crp = Cout + (size_t)crow * NOUT + bn + tc;
        #pragma unroll
        for (int j = 0; j < 8; j += 4) {
            float4 v;
            v.x = acc[i][j + 0]; v.y = acc[i][j + 1];
            v.z = acc[i][j + 2]; v.w = acc[i][j + 3];
            if (MODE == 1) {
                int gn = bn + tc + j;
                v.x += bias[gn + 0]; v.y += bias[gn + 1];
                v.z += bias[gn + 2]; v.w += bias[gn + 3];
            }
            *reinterpret_cast<float4*>(crp + j) = v;
        }
    }
}

// ---------------------------------------------------------------------------
// Windowed attention: one block per (batch, window, head).
// 256 query rows (one per thread). K/V staged in 64-key tiles in static
// shared memory (2 x 64 x 64 fp32 = 32 KB), online softmax across tiles.
// ---------------------------------------------------------------------------
__global__ __launch_bounds__(256) void attn_k()
{
    __shared__ float Ks[KT_ * HD_];
    __shared__ float Vs[KT_ * HD_];

    const int blk = blockIdx.x;
    const int h = blk % H_;
    const int w = (blk / H_) % NWIN_;
    const int b = blk / (H_ * NWIN_);
    const int rowbase = b * N_ + w * WT_;
    const int qoff = h * HD_;
    const int koff = C_ + h * HD_;
    const int voff = 2 * C_ + h * HD_;
    const int tid = threadIdx.x;

    // per-thread query row
    float q[HD_];
    {
        const float* qp = g_qkv + (size_t)(rowbase + tid) * C3_ + qoff;
        #pragma unroll
        for (int d = 0; d < HD_; d += 4)
            *reinterpret_cast<float4*>(&q[d]) = *reinterpret_cast<const float4*>(qp + d);
    }

    float o[HD_];
    #pragma unroll
    for (int d = 0; d < HD_; d++) o[d] = 0.f;
    float mmax = -1e30f, l = 0.f;

    #pragma unroll 1
    for (int t0 = 0; t0 < WT_; t0 += KT_) {
        // cooperative load of 64-key K/V tile: 64 rows x 16 float4 = 1024 float4
        __syncthreads();
        #pragma unroll
        for (int it = 0; it < 4; it++) {
            int idx = it * 256 + tid;          // 0..1023
            int j   = idx >> 4;                // 0..63
            int dq  = (idx & 15) << 2;         // 0..60
            const float* base = g_qkv + (size_t)(rowbase + t0 + j) * C3_;
            *reinterpret_cast<float4*>(&Ks[j * HD_ + dq]) =
                *reinterpret_cast<const float4*>(base + koff + dq);
            *reinterpret_cast<float4*>(&Vs[j * HD_ + dq]) =
                *reinterpret_cast<const float4*>(base + voff + dq);
        }
        __syncthreads();

        #pragma unroll 1
        for (int j0 = 0; j0 < KT_; j0 += 16) {
            float s[16];
            #pragma unroll
            for (int j = 0; j < 16; j++) {
                const float* kp = &Ks[(j0 + j) * HD_];
                float a0 = 0.f;
                #pragma unroll
                for (int d = 0; d < HD_; d += 4) {
                    float4 kv = *reinterpret_cast<const float4*>(kp + d);
                    a0 = fmaf(q[d + 0], kv.x, a0);
                    a0 = fmaf(q[d + 1], kv.y, a0);
                    a0 = fmaf(q[d + 2], kv.z, a0);
                    a0 = fmaf(q[d + 3], kv.w, a0);
                }
                s[j] = a0 * SCALE_;
            }
            float cm = mmax;
            #pragma unroll
            for (int j = 0; j < 16; j++) cm = fmaxf(cm, s[j]);
            float corr = __expf(mmax - cm);
            mmax = cm;
            l *= corr;
            #pragma unroll
            for (int d = 0; d < HD_; d++) o[d] *= corr;
            #pragma unroll
            for (int j = 0; j < 16; j++) {
                float p = __expf(s[j] - mmax);
                l += p;
                const float* vp = &Vs[(j0 + j) * HD_];
                #pragma unroll
                for (int d = 0; d < HD_; d += 4) {
                    float4 vv = *reinterpret_cast<const float4*>(vp + d);
                    o[d + 0] = fmaf(p, vv.x, o[d + 0]);
                    o[d + 1] = fmaf(p, vv.y, o[d + 1]);
                    o[d + 2] = fmaf(p, vv.z, o[d + 2]);
                    o[d + 3] = fmaf(p, vv.w, o[d + 3]);
                }
            }
        }
    }

    float inv = 1.f / l;
    float* op = g_ao + (size_t)(rowbase + tid) * C_ + h * HD_;
    #pragma unroll
    for (int d = 0; d < HD_; d += 4) {
        float4 v;
        v.x = o[d + 0] * inv; v.y = o[d + 1] * inv;
        v.z = o[d + 2] * inv; v.w = o[d + 3] * inv;
        *reinterpret_cast<float4*>(op + d) = v;
    }
}

// ---------------------------------------------------------------------------

extern "C" void kernel_launch(void* const* d_in, const int* in_sizes, int n_in,
                              void* d_out, int out_size)
{
    const float* x      = (const float*)d_in[0];
    const float* qkv_w  = (const float*)d_in[1];
    const float* proj_w = (const float*)d_in[2];
    const float* proj_b = (const float*)d_in[3];
    float* out = (float*)d_out;

    // 1) fused permute + QKV GEMM: g_qkv[p,:] = x[perm(p),:] @ qkv_w^T
    sgemm_k<C3_, 0><<<dim3(C3_ / 128, M_ / 128), 256>>>(x, qkv_w, nullptr, nullptr);

    // 2) windowed attention (static 32 KB smem, no attribute calls)
    attn_k<<<B_ * NWIN_ * H_, 256>>>();

    // 3) proj GEMM with inverse-permuted store + bias
    sgemm_k<C_, 1><<<dim3(C_ / 128, M_ / 128), 256>>>(nullptr, proj_w, proj_b, out);
}

// round 4
// speedup vs baseline: 1.8671x; 1.8671x over previous
#include <cuda_runtime.h>
#include <cuda_bf16.h>
#include <math.h>
#include <stdint.h>

#define B_    8
#define N_    4096
#define C_    768
#define H_    12
#define HD_   64
#define NWIN_ 16
#define WT_   256
#define KT_   64
#define C3_   2304
#define M_    (B_ * N_)   /* 32768 */
#define SCALE_ 0.125f

// Scratch (device globals; no allocation allowed)
__device__ float g_qkv[(size_t)M_ * C3_];  // qkv, window-permuted row order
__device__ float g_ao [(size_t)M_ * C_];   // attention output, permuted order

// permuted position p <-> original token index (involution)
__device__ __forceinline__ int perm_orig(int p) {
    int a = p >> 10, c = (p >> 8) & 3, bq = (p >> 4) & 15, d = p & 15;
    return (a << 10) | (bq << 6) | (c << 4) | d;
}

__device__ __forceinline__ uint32_t smem_u32(const void* p) {
    uint32_t a;
    asm("{ .reg .u64 t; cvta.to.shared.u64 t, %1; cvt.u32.u64 %0, t; }" : "=r"(a) : "l"(p));
    return a;
}

#define STS128(a, r0, r1, r2, r3) asm volatile( \
    "st.shared.v4.b32 [%0], {%1, %2, %3, %4};" :: "r"(a), "r"(r0), "r"(r1), "r"(r2), "r"(r3) : "memory")

#define LDM4(r, addr) asm volatile( \
    "ldmatrix.sync.aligned.m8n8.x4.shared.b16 {%0,%1,%2,%3}, [%4];" \
    : "=r"((r)[0]), "=r"((r)[1]), "=r"((r)[2]), "=r"((r)[3]) : "r"(addr))

#define MMA16816(c, a, b0, b1) asm volatile( \
    "mma.sync.aligned.m16n8k16.row.col.f32.bf16.bf16.f32 " \
    "{%0,%1,%2,%3}, {%4,%5,%6,%7}, {%8,%9}, {%0,%1,%2,%3};" \
    : "+f"((c)[0]), "+f"((c)[1]), "+f"((c)[2]), "+f"((c)[3]) \
    : "r"((a)[0]), "r"((a)[1]), "r"((a)[2]), "r"((a)[3]), "r"(b0), "r"(b1))

// fp32 -> (hi bf16, lo bf16) split of 8 elements
__device__ __forceinline__ uint32_t pk2(float a, float b) {
    __nv_bfloat16 ha = __float2bfloat16(a), hb = __float2bfloat16(b);
    return (uint32_t)__bfloat16_as_ushort(ha) | ((uint32_t)__bfloat16_as_ushort(hb) << 16);
}
__device__ __forceinline__ void cvt8(const float* f, uint4& hi, uint4& lo) {
    float r[8];
    #pragma unroll
    for (int i = 0; i < 8; i++)
        r[i] = f[i] - __bfloat162float(__float2bfloat16(f[i]));
    hi.x = pk2(f[0], f[1]); hi.y = pk2(f[2], f[3]);
    hi.z = pk2(f[4], f[5]); hi.w = pk2(f[6], f[7]);
    lo.x = pk2(r[0], r[1]); lo.y = pk2(r[2], r[3]);
    lo.z = pk2(r[4], r[5]); lo.w = pk2(r[6], r[7]);
}

// ---------------------------------------------------------------------------
// mma.sync bf16 3-term-split GEMM: C[M x NOUT] = A[M x 768] @ W[NOUT x 768]^T
// CTA tile 128x128, BK=32, 256 threads (8 warps, 64x32 warp tiles).
// Smem tiles: hi/lo bf16, row stride 40 bf16 (80 B) -> conflict-free ldmatrix.
// MODE 0: A = x with permuted row reads, C = g_qkv
// MODE 1: A = g_ao, C = out with permuted row stores, + bias
// ---------------------------------------------------------------------------
#define TS_ 40   /* smem row stride in bf16 (80 bytes) */

template<int NOUT, int MODE>
__global__ __launch_bounds__(256)
void mma_gemm_k(const float* __restrict__ Ain, const float* __restrict__ Wt,
                const float* __restrict__ bias, float* __restrict__ Cext)
{
    __shared__ __align__(16) __nv_bfloat16 sAhi[128 * TS_];
    __shared__ __align__(16) __nv_bfloat16 sAlo[128 * TS_];
    __shared__ __align__(16) __nv_bfloat16 sBhi[128 * TS_];
    __shared__ __align__(16) __nv_bfloat16 sBlo[128 * TS_];

    const int tid  = threadIdx.x;
    const int wid  = tid >> 5;
    const int lane = tid & 31;
    const int bm   = blockIdx.y * 128;
    const int bn   = blockIdx.x * 128;
    const int wm   = (wid & 1) * 64;    // warp row offset
    const int wn   = (wid >> 1) * 32;   // warp col offset

    const float* A    = (MODE == 0) ? Ain : g_ao;
    float*       Cout = (MODE == 0) ? g_qkv : Cext;

    const uint32_t aAhi = smem_u32(sAhi), aAlo = smem_u32(sAlo);
    const uint32_t aBhi = smem_u32(sBhi), aBlo = smem_u32(sBlo);

    // per-lane ldmatrix offsets (bytes)
    const int g  = lane >> 3, lr = lane & 7;
    const uint32_t aoff = (uint32_t)((lr + (g & 1) * 8) * 80 + (g >> 1) * 16);
    const uint32_t boff = (uint32_t)((lr + (g >> 1) * 8) * 80 + (g & 1) * 16);

    // load-phase indices: idx = it*256+tid -> row r (0..127), group q (0..3)
    int arowg[2];
    #pragma unroll
    for (int it = 0; it < 2; it++) {
        int idx = it * 256 + tid;
        int r = idx >> 2;
        int gm = bm + r;
        arowg[it] = (MODE == 0) ? ((gm & ~4095) + perm_orig(gm & 4095)) : gm;
    }

    float acc[4][4][4];
    #pragma unroll
    for (int i = 0; i < 4; i++)
        #pragma unroll
        for (int j = 0; j < 4; j++)
            #pragma unroll
            for (int v = 0; v < 4; v++) acc[i][j][v] = 0.f;

    #pragma unroll 1
    for (int kc = 0; kc < C_ / 32; kc++) {
        const int k0 = kc * 32;
        if (kc) __syncthreads();

        // ---- batched global loads (8 LDG.128 in flight) ----
        float fa[2][8], fb[2][8];
        #pragma unroll
        for (int it = 0; it < 2; it++) {
            int idx = it * 256 + tid;
            int r = idx >> 2, q = idx & 3;
            const float* sA = A + (size_t)arowg[it] * C_ + k0 + q * 8;
            const float* sB = Wt + (size_t)(bn + r) * C_ + k0 + q * 8;
            *reinterpret_cast<float4*>(&fa[it][0]) = *reinterpret_cast<const float4*>(sA);
            *reinterpret_cast<float4*>(&fa[it][4]) = *reinterpret_cast<const float4*>(sA + 4);
            *reinterpret_cast<float4*>(&fb[it][0]) = *reinterpret_cast<const float4*>(sB);
            *reinterpret_cast<float4*>(&fb[it][4]) = *reinterpret_cast<const float4*>(sB + 4);
        }
        // ---- convert + store to smem ----
        #pragma unroll
        for (int it = 0; it < 2; it++) {
            int idx = it * 256 + tid;
            int r = idx >> 2, q = idx & 3;
            uint32_t off = (uint32_t)(r * 80 + q * 16);
            uint4 hi, lo;
            cvt8(fa[it], hi, lo);
            STS128(aAhi + off, hi.x, hi.y, hi.z, hi.w);
            STS128(aAlo + off, lo.x, lo.y, lo.z, lo.w);
            cvt8(fb[it], hi, lo);
            STS128(aBhi + off, hi.x, hi.y, hi.z, hi.w);
            STS128(aBlo + off, lo.x, lo.y, lo.z, lo.w);
        }
        __syncthreads();

        // ---- compute: 2 k-steps of m16n8k16 ----
        #pragma unroll
        for (int kb = 0; kb < 2; kb++) {
            uint32_t ah[4][4], al[4][4], bh[2][4], bl[2][4];
            #pragma unroll
            for (int mf = 0; mf < 4; mf++) {
                uint32_t base = (uint32_t)((wm + mf * 16) * 80 + kb * 32) + aoff;
                LDM4(ah[mf], aAhi + base);
                LDM4(al[mf], aAlo + base);
            }
            #pragma unroll
            for (int nb = 0; nb < 2; nb++) {
                uint32_t base = (uint32_t)((wn + nb * 16) * 80 + kb * 32) + boff;
                LDM4(bh[nb], aBhi + base);
                LDM4(bl[nb], aBlo + base);
            }
            #pragma unroll
            for (int mf = 0; mf < 4; mf++)
                #pragma unroll
                for (int nf = 0; nf < 4; nf++) {
                    uint32_t* bhp = &bh[nf >> 1][(nf & 1) * 2];
                    uint32_t* blp = &bl[nf >> 1][(nf & 1) * 2];
                    MMA16816(acc[mf][nf], ah[mf], bhp[0], bhp[1]);
                    MMA16816(acc[mf][nf], ah[mf], blp[0], blp[1]);
                    MMA16816(acc[mf][nf], al[mf], bhp[0], bhp[1]);
                }
        }
    }

    // ---- epilogue ----
    const int l4 = lane >> 2, l2 = (lane & 3) * 2;
    float2 bb[4];
    if (MODE == 1) {
        #pragma unroll
        for (int nf = 0; nf < 4; nf++)
            bb[nf] = *reinterpret_cast<const float2*>(bias + bn + wn + nf * 8 + l2);
    }
    #pragma unroll
    for (int mf = 0; mf < 4; mf++) {
        int gm0 = bm + wm + mf * 16 + l4;
        int gm1 = gm0 + 8;
        int cr0 = (MODE == 1) ? ((gm0 & ~4095) + perm_orig(gm0 & 4095)) : gm0;
        int cr1 = (MODE == 1) ? ((gm1 & ~4095) + perm_orig(gm1 & 4095)) : gm1;
        #pragma unroll
        for (int nf = 0; nf < 4; nf++) {
            int gn = bn + wn + nf * 8 + l2;
            float2 v0, v1;
            v0.x = acc[mf][nf][0]; v0.y = acc[mf][nf][1];
            v1.x = acc[mf][nf][2]; v1.y = acc[mf][nf][3];
            if (MODE == 1) {
                v0.x += bb[nf].x; v0.y += bb[nf].y;
                v1.x += bb[nf].x; v1.y += bb[nf].y;
            }
            *reinterpret_cast<float2*>(Cout + (size_t)cr0 * NOUT + gn) = v0;
            *reinterpret_cast<float2*>(Cout + (size_t)cr1 * NOUT + gn) = v1;
        }
    }
}

// ---------------------------------------------------------------------------
// Windowed attention (unchanged): one block per (batch, window, head),
// fp32, 64-key smem tiles, online softmax, one query row per thread.
// ---------------------------------------------------------------------------
__global__ __launch_bounds__(256) void attn_k()
{
    __shared__ float Ks[KT_ * HD_];
    __shared__ float Vs[KT_ * HD_];

    const int blk = blockIdx.x;
    const int h = blk % H_;
    const int w = (blk / H_) % NWIN_;
    const int b = blk / (H_ * NWIN_);
    const int rowbase = b * N_ + w * WT_;
    const int qoff = h * HD_;
    const int koff = C_ + h * HD_;
    const int voff = 2 * C_ + h * HD_;
    const int tid = threadIdx.x;

    float q[HD_];
    {
        const float* qp = g_qkv + (size_t)(rowbase + tid) * C3_ + qoff;
        #pragma unroll
        for (int d = 0; d < HD_; d += 4)
            *reinterpret_cast<float4*>(&q[d]) = *reinterpret_cast<const float4*>(qp + d);
    }

    float o[HD_];
    #pragma unroll
    for (int d = 0; d < HD_; d++) o[d] = 0.f;
    float mmax = -1e30f, l = 0.f;

    #pragma unroll 1
    for (int t0 = 0; t0 < WT_; t0 += KT_) {
        __syncthreads();
        #pragma unroll
        for (int it = 0; it < 4; it++) {
            int idx = it * 256 + tid;
            int j   = idx >> 4;
            int dq  = (idx & 15) << 2;
            const float* base = g_qkv + (size_t)(rowbase + t0 + j) * C3_;
            *reinterpret_cast<float4*>(&Ks[j * HD_ + dq]) =
                *reinterpret_cast<const float4*>(base + koff + dq);
            *reinterpret_cast<float4*>(&Vs[j * HD_ + dq]) =
                *reinterpret_cast<const float4*>(base + voff + dq);
        }
        __syncthreads();

        #pragma unroll 1
        for (int j0 = 0; j0 < KT_; j0 += 16) {
            float s[16];
            #pragma unroll
            for (int j = 0; j < 16; j++) {
                const float* kp = &Ks[(j0 + j) * HD_];
                float a0 = 0.f;
                #pragma unroll
                for (int d = 0; d < HD_; d += 4) {
                    float4 kv = *reinterpret_cast<const float4*>(kp + d);
                    a0 = fmaf(q[d + 0], kv.x, a0);
                    a0 = fmaf(q[d + 1], kv.y, a0);
                    a0 = fmaf(q[d + 2], kv.z, a0);
                    a0 = fmaf(q[d + 3], kv.w, a0);
                }
                s[j] = a0 * SCALE_;
            }
            float cm = mmax;
            #pragma unroll
            for (int j = 0; j < 16; j++) cm = fmaxf(cm, s[j]);
            float corr = __expf(mmax - cm);
            mmax = cm;
            l *= corr;
            #pragma unroll
            for (int d = 0; d < HD_; d++) o[d] *= corr;
            #pragma unroll
            for (int j = 0; j < 16; j++) {
                float p = __expf(s[j] - mmax);
                l += p;
                const float* vp = &Vs[(j0 + j) * HD_];
                #pragma unroll
                for (int d = 0; d < HD_; d += 4) {
                    float4 vv = *reinterpret_cast<const float4*>(vp + d);
                    o[d + 0] = fmaf(p, vv.x, o[d + 0]);
                    o[d + 1] = fmaf(p, vv.y, o[d + 1]);
                    o[d + 2] = fmaf(p, vv.z, o[d + 2]);
                    o[d + 3] = fmaf(p, vv.w, o[d + 3]);
                }
            }
        }
    }

    float inv = 1.f / l;
    float* op = g_ao + (size_t)(rowbase + tid) * C_ + h * HD_;
    #pragma unroll
    for (int d = 0; d < HD_; d += 4) {
        float4 v;
        v.x = o[d + 0] * inv; v.y = o[d + 1] * inv;
        v.z = o[d + 2] * inv; v.w = o[d + 3] * inv;
        *reinterpret_cast<float4*>(op + d) = v;
    }
}

// ---------------------------------------------------------------------------

extern "C" void kernel_launch(void* const* d_in, const int* in_sizes, int n_in,
                              void* d_out, int out_size)
{
    const float* x      = (const float*)d_in[0];
    const float* qkv_w  = (const float*)d_in[1];
    const float* proj_w = (const float*)d_in[2];
    const float* proj_b = (const float*)d_in[3];
    float* out = (float*)d_out;

    // 1) fused permute + QKV GEMM (mma.sync bf16 3-term split)
    mma_gemm_k<C3_, 0><<<dim3(C3_ / 128, M_ / 128), 256>>>(x, qkv_w, nullptr, nullptr);

    // 2) windowed attention (fp32)
    attn_k<<<B_ * NWIN_ * H_, 256>>>();

    // 3) proj GEMM with inverse-permuted store + bias
    mma_gemm_k<C_, 1><<<dim3(C_ / 128, M_ / 128), 256>>>(nullptr, proj_w, proj_b, out);
}

// round 6
// speedup vs baseline: 2.5548x; 1.3683x over previous
#include <cuda_runtime.h>
#include <cuda_bf16.h>
#include <math.h>
#include <stdint.h>

#define B_    8
#define N_    4096
#define C_    768
#define H_    12
#define HD_   64
#define NWIN_ 16
#define WT_   256
#define C3_   2304
#define M_    (B_ * N_)   /* 32768 */
#define SCALE_ 0.125f

// Scratch (device globals; no allocation allowed)
__device__ float g_qkv[(size_t)M_ * C3_];  // qkv, window-permuted row order
__device__ float g_ao [(size_t)M_ * C_];   // attention output, permuted order

// permuted position p <-> original token index (involution)
__device__ __forceinline__ int perm_orig(int p) {
    int a = p >> 10, c = (p >> 8) & 3, bq = (p >> 4) & 15, d = p & 15;
    return (a << 10) | (bq << 6) | (c << 4) | d;
}

__device__ __forceinline__ uint32_t smem_u32(const void* p) {
    uint32_t a;
    asm("{ .reg .u64 t; cvta.to.shared.u64 t, %1; cvt.u32.u64 %0, t; }" : "=r"(a) : "l"(p));
    return a;
}

#define STS128(a, r0, r1, r2, r3) asm volatile( \
    "st.shared.v4.b32 [%0], {%1, %2, %3, %4};" :: "r"(a), "r"(r0), "r"(r1), "r"(r2), "r"(r3) : "memory")
#define STS64(a, r0, r1) asm volatile( \
    "st.shared.v2.b32 [%0], {%1, %2};" :: "r"(a), "r"(r0), "r"(r1) : "memory")

#define LDM4(r, addr) asm volatile( \
    "ldmatrix.sync.aligned.m8n8.x4.shared.b16 {%0,%1,%2,%3}, [%4];" \
    : "=r"((r)[0]), "=r"((r)[1]), "=r"((r)[2]), "=r"((r)[3]) : "r"(addr))

#define LDM4T(r, addr) asm volatile( \
    "ldmatrix.sync.aligned.m8n8.x4.trans.shared.b16 {%0,%1,%2,%3}, [%4];" \
    : "=r"((r)[0]), "=r"((r)[1]), "=r"((r)[2]), "=r"((r)[3]) : "r"(addr))

#define MMA16816(c, a, b0, b1) asm volatile( \
    "mma.sync.aligned.m16n8k16.row.col.f32.bf16.bf16.f32 " \
    "{%0,%1,%2,%3}, {%4,%5,%6,%7}, {%8,%9}, {%0,%1,%2,%3};" \
    : "+f"((c)[0]), "+f"((c)[1]), "+f"((c)[2]), "+f"((c)[3]) \
    : "r"((a)[0]), "r"((a)[1]), "r"((a)[2]), "r"((a)[3]), "r"(b0), "r"(b1))

// fp32 -> (hi bf16, lo bf16) split helpers
__device__ __forceinline__ uint32_t pk2(float a, float b) {
    __nv_bfloat16 ha = __float2bfloat16(a), hb = __float2bfloat16(b);
    return (uint32_t)__bfloat16_as_ushort(ha) | ((uint32_t)__bfloat16_as_ushort(hb) << 16);
}
__device__ __forceinline__ void splitpk(float a, float b, uint32_t& hi, uint32_t& lo) {
    __nv_bfloat16 ha = __float2bfloat16(a), hb = __float2bfloat16(b);
    hi = (uint32_t)__bfloat16_as_ushort(ha) | ((uint32_t)__bfloat16_as_ushort(hb) << 16);
    lo = pk2(a - __bfloat162float(ha), b - __bfloat162float(hb));
}
__device__ __forceinline__ void cvt8(const float* f, uint4& hi, uint4& lo) {
    float r[8];
    #pragma unroll
    for (int i = 0; i < 8; i++)
        r[i] = f[i] - __bfloat162float(__float2bfloat16(f[i]));
    hi.x = pk2(f[0], f[1]); hi.y = pk2(f[2], f[3]);
    hi.z = pk2(f[4], f[5]); hi.w = pk2(f[6], f[7]);
    lo.x = pk2(r[0], r[1]); lo.y = pk2(r[2], r[3]);
    lo.z = pk2(r[4], r[5]); lo.w = pk2(r[6], r[7]);
}

// ---------------------------------------------------------------------------
// mma.sync bf16 3-term-split GEMM (unchanged from R4, validated)
// ---------------------------------------------------------------------------
#define TS_ 40   /* smem row stride in bf16 (80 bytes) */

template<int NOUT, int MODE>
__global__ __launch_bounds__(256)
void mma_gemm_k(const float* __restrict__ Ain, const float* __restrict__ Wt,
                const float* __restrict__ bias, float* __restrict__ Cext)
{
    __shared__ __align__(16) __nv_bfloat16 sAhi[128 * TS_];
    __shared__ __align__(16) __nv_bfloat16 sAlo[128 * TS_];
    __shared__ __align__(16) __nv_bfloat16 sBhi[128 * TS_];
    __shared__ __align__(16) __nv_bfloat16 sBlo[128 * TS_];

    const int tid  = threadIdx.x;
    const int wid  = tid >> 5;
    const int lane = tid & 31;
    const int bm   = blockIdx.y * 128;
    const int bn   = blockIdx.x * 128;
    const int wm   = (wid & 1) * 64;
    const int wn   = (wid >> 1) * 32;

    const float* A    = (MODE == 0) ? Ain : g_ao;
    float*       Cout = (MODE == 0) ? g_qkv : Cext;

    const uint32_t aAhi = smem_u32(sAhi), aAlo = smem_u32(sAlo);
    const uint32_t aBhi = smem_u32(sBhi), aBlo = smem_u32(sBlo);

    const int g  = lane >> 3, lr = lane & 7;
    const uint32_t aoff = (uint32_t)((lr + (g & 1) * 8) * 80 + (g >> 1) * 16);
    const uint32_t boff = (uint32_t)((lr + (g >> 1) * 8) * 80 + (g & 1) * 16);

    int arowg[2];
    #pragma unroll
    for (int it = 0; it < 2; it++) {
        int idx = it * 256 + tid;
        int r = idx >> 2;
        int gm = bm + r;
        arowg[it] = (MODE == 0) ? ((gm & ~4095) + perm_orig(gm & 4095)) : gm;
    }

    float acc[4][4][4];
    #pragma unroll
    for (int i = 0; i < 4; i++)
        #pragma unroll
        for (int j = 0; j < 4; j++)
            #pragma unroll
            for (int v = 0; v < 4; v++) acc[i][j][v] = 0.f;

    #pragma unroll 1
    for (int kc = 0; kc < C_ / 32; kc++) {
        const int k0 = kc * 32;
        if (kc) __syncthreads();

        float fa[2][8], fb[2][8];
        #pragma unroll
        for (int it = 0; it < 2; it++) {
            int idx = it * 256 + tid;
            int r = idx >> 2, q = idx & 3;
            const float* sA = A + (size_t)arowg[it] * C_ + k0 + q * 8;
            const float* sB = Wt + (size_t)(bn + r) * C_ + k0 + q * 8;
            *reinterpret_cast<float4*>(&fa[it][0]) = *reinterpret_cast<const float4*>(sA);
            *reinterpret_cast<float4*>(&fa[it][4]) = *reinterpret_cast<const float4*>(sA + 4);
            *reinterpret_cast<float4*>(&fb[it][0]) = *reinterpret_cast<const float4*>(sB);
            *reinterpret_cast<float4*>(&fb[it][4]) = *reinterpret_cast<const float4*>(sB + 4);
        }
        #pragma unroll
        for (int it = 0; it < 2; it++) {
            int idx = it * 256 + tid;
            int r = idx >> 2, q = idx & 3;
            uint32_t off = (uint32_t)(r * 80 + q * 16);
            uint4 hi, lo;
            cvt8(fa[it], hi, lo);
            STS128(aAhi + off, hi.x, hi.y, hi.z, hi.w);
            STS128(aAlo + off, lo.x, lo.y, lo.z, lo.w);
            cvt8(fb[it], hi, lo);
            STS128(aBhi + off, hi.x, hi.y, hi.z, hi.w);
            STS128(aBlo + off, lo.x, lo.y, lo.z, lo.w);
        }
        __syncthreads();

        #pragma unroll
        for (int kb = 0; kb < 2; kb++) {
            uint32_t ah[4][4], al[4][4], bh[2][4], bl[2][4];
            #pragma unroll
            for (int mf = 0; mf < 4; mf++) {
                uint32_t base = (uint32_t)((wm + mf * 16) * 80 + kb * 32) + aoff;
                LDM4(ah[mf], aAhi + base);
                LDM4(al[mf], aAlo + base);
            }
            #pragma unroll
            for (int nb = 0; nb < 2; nb++) {
                uint32_t base = (uint32_t)((wn + nb * 16) * 80 + kb * 32) + boff;
                LDM4(bh[nb], aBhi + base);
                LDM4(bl[nb], aBlo + base);
            }
            #pragma unroll
            for (int mf = 0; mf < 4; mf++)
                #pragma unroll
                for (int nf = 0; nf < 4; nf++) {
                    uint32_t* bhp = &bh[nf >> 1][(nf & 1) * 2];
                    uint32_t* blp = &bl[nf >> 1][(nf & 1) * 2];
                    MMA16816(acc[mf][nf], ah[mf], bhp[0], bhp[1]);
                    MMA16816(acc[mf][nf], ah[mf], blp[0], blp[1]);
                    MMA16816(acc[mf][nf], al[mf], bhp[0], bhp[1]);
                }
        }
    }

    const int l4 = lane >> 2, l2 = (lane & 3) * 2;
    float2 bb[4];
    if (MODE == 1) {
        #pragma unroll
        for (int nf = 0; nf < 4; nf++)
            bb[nf] = *reinterpret_cast<const float2*>(bias + bn + wn + nf * 8 + l2);
    }
    #pragma unroll
    for (int mf = 0; mf < 4; mf++) {
        int gm0 = bm + wm + mf * 16 + l4;
        int gm1 = gm0 + 8;
        int cr0 = (MODE == 1) ? ((gm0 & ~4095) + perm_orig(gm0 & 4095)) : gm0;
        int cr1 = (MODE == 1) ? ((gm1 & ~4095) + perm_orig(gm1 & 4095)) : gm1;
        #pragma unroll
        for (int nf = 0; nf < 4; nf++) {
            int gn = bn + wn + nf * 8 + l2;
            float2 v0, v1;
            v0.x = acc[mf][nf][0]; v0.y = acc[mf][nf][1];
            v1.x = acc[mf][nf][2]; v1.y = acc[mf][nf][3];
            if (MODE == 1) {
                v0.x += bb[nf].x; v0.y += bb[nf].y;
                v1.x += bb[nf].x; v1.y += bb[nf].y;
            }
            *reinterpret_cast<float2*>(Cout + (size_t)cr0 * NOUT + gn) = v0;
            *reinterpret_cast<float2*>(Cout + (size_t)cr1 * NOUT + gn) = v1;
        }
    }
}

// ---------------------------------------------------------------------------
// Tensor-core windowed attention (bf16 3-term split, flash-style).
// Block = 256 threads (8 warps), 128 queries of one (b,w,h); keys in 4
// chunks of 64. Q*K^T: proven GEMM fragment path. P: accum->A-frag in regs.
// V: row-major smem, B-frags via ldmatrix.trans.
// Smem: Q stage (128x72 hi/lo) unioned with K + V chunks (64x72 hi/lo each).
// ---------------------------------------------------------------------------
#define SQT_ 72          /* bf16 row stride (144 B, conflict-free ldmatrix) */

__global__ __launch_bounds__(256) void attn_k()
{
    __shared__ __align__(16) __nv_bfloat16 smb[18432];  // 36.9 KB

    const int tid = threadIdx.x, wid = tid >> 5, lane = tid & 31;
    const int blk = blockIdx.x;
    const int half = blk & 1;
    const int t = blk >> 1;
    const int h = t % H_;
    const int w = (t / H_) % NWIN_;
    const int b = t / (H_ * NWIN_);
    const int rowbase = b * N_ + w * WT_;
    const int qrow0 = rowbase + half * 128;
    const int qoff = h * HD_, koff = C_ + h * HD_, voff = 2 * C_ + h * HD_;

    const uint32_t sb = smem_u32(smb);
    const uint32_t aQhi = sb,                aQlo = sb + 9216 * 2;
    const uint32_t aKhi = sb,                aKlo = sb + 4608 * 2;
    const uint32_t aVhi = sb + 9216 * 2,     aVlo = sb + 13824 * 2;

    const int g = lane >> 3, lr = lane & 7;
    const uint32_t aoff = (uint32_t)((lr + (g & 1) * 8) * 144 + (g >> 1) * 16);
    const uint32_t boff = (uint32_t)((lr + (g >> 1) * 8) * 144 + (g & 1) * 16);

    // ---- stage Q (pre-scaled by SCALE_), hi/lo split ----
    #pragma unroll
    for (int it = 0; it < 8; it++) {
        int idx = it * 256 + tid;
        int r = idx >> 4, gq = idx & 15;
        float4 f = *reinterpret_cast<const float4*>(
            g_qkv + (size_t)(qrow0 + r) * C3_ + qoff + gq * 4);
        f.x *= SCALE_; f.y *= SCALE_; f.z *= SCALE_; f.w *= SCALE_;
        uint32_t h0, h1, l0, l1;
        splitpk(f.x, f.y, h0, l0); splitpk(f.z, f.w, h1, l1);
        uint32_t off = (uint32_t)(r * SQT_ + gq * 4) * 2;
        STS64(aQhi + off, h0, h1);
        STS64(aQlo + off, l0, l1);
    }
    __syncthreads();

    // ---- extract Q fragments (warp rows wid*16..+16, k = 64) ----
    uint32_t qh[4][4], ql[4][4];
    #pragma unroll
    for (int kb = 0; kb < 4; kb++) {
        uint32_t base = (uint32_t)(wid * 16 * 144 + kb * 32) + aoff;
        LDM4(qh[kb], aQhi + base);
        LDM4(ql[kb], aQlo + base);
    }
    __syncthreads();

    float od[8][4];
    #pragma unroll
    for (int j = 0; j < 8; j++)
        #pragma unroll
        for (int v = 0; v < 4; v++) od[j][v] = 0.f;
    float m0 = -1e30f, m1 = -1e30f, l0 = 0.f, l1 = 0.f;

    #pragma unroll 1
    for (int c = 0; c < 4; c++) {
        const int kc = c * 64;
        // ---- stage K and V chunk (64 keys x 64 d) ----
        #pragma unroll
        for (int it = 0; it < 4; it++) {
            int idx = it * 256 + tid;
            int r = idx >> 4, gq = idx & 15;
            const float* bp = g_qkv + (size_t)(rowbase + kc + r) * C3_;
            float4 fk = *reinterpret_cast<const float4*>(bp + koff + gq * 4);
            float4 fv = *reinterpret_cast<const float4*>(bp + voff + gq * 4);
            uint32_t h0, h1, ll0, ll1;
            uint32_t off = (uint32_t)(r * SQT_ + gq * 4) * 2;
            splitpk(fk.x, fk.y, h0, ll0); splitpk(fk.z, fk.w, h1, ll1);
            STS64(aKhi + off, h0, h1); STS64(aKlo + off, ll0, ll1);
            splitpk(fv.x, fv.y, h0, ll0); splitpk(fv.z, fv.w, h1, ll1);
            STS64(aVhi + off, h0, h1); STS64(aVlo + off, ll0, ll1);
        }
        __syncthreads();

        // ---- S = Q*K^T (3-term split), accum s[8][4] over 64 keys ----
        float s[8][4];
        #pragma unroll
        for (int j = 0; j < 8; j++)
            #pragma unroll
            for (int v = 0; v < 4; v++) s[j][v] = 0.f;
        #pragma unroll
        for (int kb = 0; kb < 4; kb++) {
            #pragma unroll
            for (int nt = 0; nt < 4; nt++) {
                uint32_t base = (uint32_t)(nt * 16 * 144 + kb * 32);
                uint32_t kh[4], kl[4];
                LDM4(kh, aKhi + base + boff);
                LDM4(kl, aKlo + base + boff);
                MMA16816(s[2 * nt],     qh[kb], kh[0], kh[1]);
                MMA16816(s[2 * nt],     qh[kb], kl[0], kl[1]);
                MMA16816(s[2 * nt],     ql[kb], kh[0], kh[1]);
                MMA16816(s[2 * nt + 1], qh[kb], kh[2], kh[3]);
                MMA16816(s[2 * nt + 1], qh[kb], kl[2], kl[3]);
                MMA16816(s[2 * nt + 1], ql[kb], kh[2], kh[3]);
            }
        }

        // ---- online softmax (rows r = lane>>2 and r+8) ----
        float cm0 = -1e30f, cm1 = -1e30f;
        #pragma unroll
        for (int j = 0; j < 8; j++) {
            cm0 = fmaxf(cm0, fmaxf(s[j][0], s[j][1]));
            cm1 = fmaxf(cm1, fmaxf(s[j][2], s[j][3]));
        }
        cm0 = fmaxf(cm0, __shfl_xor_sync(0xffffffffu, cm0, 1));
        cm0 = fmaxf(cm0, __shfl_xor_sync(0xffffffffu, cm0, 2));
        cm1 = fmaxf(cm1, __shfl_xor_sync(0xffffffffu, cm1, 1));
        cm1 = fmaxf(cm1, __shfl_xor_sync(0xffffffffu, cm1, 2));
        float mn0 = fmaxf(m0, cm0), mn1 = fmaxf(m1, cm1);
        float corr0 = __expf(m0 - mn0), corr1 = __expf(m1 - mn1);
        m0 = mn0; m1 = mn1;
        float sum0 = 0.f, sum1 = 0.f;
        #pragma unroll
        for (int j = 0; j < 8; j++) {
            s[j][0] = __expf(s[j][0] - mn0);
            s[j][1] = __expf(s[j][1] - mn0);
            s[j][2] = __expf(s[j][2] - mn1);
            s[j][3] = __expf(s[j][3] - mn1);
            sum0 += s[j][0] + s[j][1];
            sum1 += s[j][2] + s[j][3];
        }
        sum0 += __shfl_xor_sync(0xffffffffu, sum0, 1);
        sum0 += __shfl_xor_sync(0xffffffffu, sum0, 2);
        sum1 += __shfl_xor_sync(0xffffffffu, sum1, 1);
        sum1 += __shfl_xor_sync(0xffffffffu, sum1, 2);
        l0 = l0 * corr0 + sum0;
        l1 = l1 * corr1 + sum1;
        #pragma unroll
        for (int j = 0; j < 8; j++) {
            od[j][0] *= corr0; od[j][1] *= corr0;
            od[j][2] *= corr1; od[j][3] *= corr1;
        }

        // ---- O += P*V : P accum->A-frags (hi/lo), V via ldmatrix.trans ----
        #pragma unroll
        for (int kb = 0; kb < 4; kb++) {
            uint32_t ph[4], pl[4];
            splitpk(s[2 * kb][0],     s[2 * kb][1],     ph[0], pl[0]);
            splitpk(s[2 * kb][2],     s[2 * kb][3],     ph[1], pl[1]);
            splitpk(s[2 * kb + 1][0], s[2 * kb + 1][1], ph[2], pl[2]);
            splitpk(s[2 * kb + 1][2], s[2 * kb + 1][3], ph[3], pl[3]);
            #pragma unroll
            for (int dt = 0; dt < 4; dt++) {
                uint32_t base = (uint32_t)(kb * 16 * 144 + dt * 32);
                uint32_t vh[4], vl[4];
                LDM4T(vh, aVhi + base + aoff);
                LDM4T(vl, aVlo + base + aoff);
                MMA16816(od[2 * dt],     ph, vh[0], vh[1]);
                MMA16816(od[2 * dt],     ph, vl[0], vl[1]);
                MMA16816(od[2 * dt],     pl, vh[0], vh[1]);
                MMA16816(od[2 * dt + 1], ph, vh[2], vh[3]);
                MMA16816(od[2 * dt + 1], ph, vl[2], vl[3]);
                MMA16816(od[2 * dt + 1], pl, vh[2], vh[3]);
            }
        }
        __syncthreads();
    }

    // ---- epilogue: normalize + store ----
    const float inv0 = 1.f / l0, inv1 = 1.f / l1;
    const int r = lane >> 2, tt = lane & 3;
    const int gr0 = qrow0 + wid * 16 + r;
    const int gr1 = gr0 + 8;
    float* op0 = g_ao + (size_t)gr0 * C_ + h * HD_;
    float* op1 = g_ao + (size_t)gr1 * C_ + h * HD_;
    #pragma unroll
    for (int j = 0; j < 8; j++) {
        int d = j * 8 + tt * 2;
        float2 v0, v1;
        v0.x = od[j][0] * inv0; v0.y = od[j][1] * inv0;
        v1.x = od[j][2] * inv1; v1.y = od[j][3] * inv1;
        *reinterpret_cast<float2*>(op0 + d) = v0;
        *reinterpret_cast<float2*>(op1 + d) = v1;
    }
}

// ---------------------------------------------------------------------------

extern "C" void kernel_launch(void* const* d_in, const int* in_sizes, int n_in,
                              void* d_out, int out_size)
{
    const float* x      = (const float*)d_in[0];
    const float* qkv_w  = (const float*)d_in[1];
    const float* proj_w = (const float*)d_in[2];
    const float* proj_b = (const float*)d_in[3];
    float* out = (float*)d_out;

    // 1) fused permute + QKV GEMM (mma.sync bf16 3-term split)
    mma_gemm_k<C3_, 0><<<dim3(C3_ / 128, M_ / 128), 256>>>(x, qkv_w, nullptr, nullptr);

    // 2) tensor-core windowed attention (2 blocks per (b,w,h))
    attn_k<<<B_ * NWIN_ * H_ * 2, 256>>>();

    // 3) proj GEMM with inverse-permuted store + bias
    mma_gemm_k<C_, 1><<<dim3(C_ / 128, M_ / 128), 256>>>(nullptr, proj_w, proj_b, out);
}